// round 5
// baseline (speedup 1.0000x reference)
#include <cuda_runtime.h>
#include <math.h>

#define BB 32
#define HH 256
#define LL 2048
#define NS 64
#define FF 32
#define BHL (BB*HH*LL)

typedef unsigned long long u64;

// ---------------- f32x2 helpers ----------------
__device__ __forceinline__ u64 pk2(float lo, float hi) {
    u64 r; asm("mov.b64 %0, {%1, %2};" : "=l"(r) : "f"(lo), "f"(hi)); return r;
}
__device__ __forceinline__ void up2(u64 v, float& a, float& b) {
    asm("mov.b64 {%0, %1}, %2;" : "=f"(a), "=f"(b) : "l"(v));
}
__device__ __forceinline__ u64 fma2(u64 a, u64 b, u64 c) {
    u64 d; asm("fma.rn.f32x2 %0, %1, %2, %3;" : "=l"(d) : "l"(a), "l"(b), "l"(c)); return d;
}
__device__ __forceinline__ u64 mul2(u64 a, u64 b) {
    u64 d; asm("mul.rn.f32x2 %0, %1, %2;" : "=l"(d) : "l"(a), "l"(b)); return d;
}

__device__ __forceinline__ float gatef(float o) {
    float u = __expf(fminf(-o, 25.f));
    float u2 = u * u;
    return (1.f - u2) / ((1.f + u2) * (1.f + u));
}

// ---------------- scratch ----------------
__device__ float g_tb[BB*HH];
__device__ float g_wr[HH*NS], g_wi[HH*NS];
__device__ float g_c0r[HH*NS], g_c0i[HH*NS], g_c1r[HH*NS], g_c1i[HH*NS];
__device__ float g_z [BHL];
__device__ float g_yf[BHL];
__device__ float g_yb[BHL];   // holds yb + D*z

// ---------------- t @ Wt^T + bt ----------------
__global__ void k_tb(const float* __restrict__ t, const float* __restrict__ Wt,
                     const float* __restrict__ bt)
{
    __shared__ float ts[HH];
    int b = blockIdx.x, h = threadIdx.x;
    ts[h] = t[b*HH + h];
    __syncthreads();
    float acc = bt[h];
    const float* wrow = Wt + (size_t)h*HH;
    #pragma unroll 8
    for (int k = 0; k < HH; k++) acc = fmaf(ts[k], wrow[k], acc);
    g_tb[b*HH + h] = acc;
}

// ---------------- SSM parameter prep ----------------
__global__ void k_ssm(const float* __restrict__ log_dt, const float* __restrict__ logA_real,
                      const float* __restrict__ A_imag, const float* __restrict__ C_re,
                      const float* __restrict__ C_im)
{
    int i = blockIdx.x*blockDim.x + threadIdx.x;
    if (i >= HH*NS) return;
    int h = i / NS;
    float dt = expf(log_dt[h]);
    float Ar = -expf(logA_real[i]);
    float Ai = A_imag[i];
    float dr = dt*Ar, di = dt*Ai;
    float er = expf(dr);
    float wr = er*cosf(di), wi = er*sinf(di);
    g_wr[i] = wr; g_wi[i] = wi;
    float Er = wr - 1.0f, Ei = wi;
    float inv = 1.0f/(Ar*Ar + Ai*Ai);
    float qr = (Er*Ar + Ei*Ai)*inv;
    float qi = (Ei*Ar - Er*Ai)*inv;
    {
        float cr = C_re[i], ci = C_im[i];
        g_c0r[i] = 2.0f*(cr*qr - ci*qi);
        g_c0i[i] = 2.0f*(cr*qi + ci*qr);
    }
    {
        float cr = C_re[HH*NS + i], ci = C_im[HH*NS + i];
        g_c1r[i] = 2.0f*(cr*qr - ci*qi);
        g_c1i[i] = 2.0f*(cr*qi + ci*qr);
    }
}

// ---------------- LayerNorm over H -> z ----------------
__global__ void k_ln(const float* __restrict__ x, const float* __restrict__ ln_g,
                     const float* __restrict__ ln_b)
{
    __shared__ float tbs[HH], gs[HH], bs[HH];
    int b = blockIdx.y;
    int l = blockIdx.x*256 + threadIdx.x;
    tbs[threadIdx.x] = g_tb[b*HH + threadIdx.x];
    gs[threadIdx.x]  = ln_g[threadIdx.x];
    bs[threadIdx.x]  = ln_b[threadIdx.x];
    __syncthreads();
    const float* xb = x + (size_t)b*HH*LL + l;
    float s = 0.f, ss = 0.f;
    #pragma unroll 8
    for (int h = 0; h < HH; h++) {
        float v = xb[(size_t)h*LL] + tbs[h];
        s += v; ss = fmaf(v, v, ss);
    }
    float mu  = s * (1.0f/HH);
    float var = ss*(1.0f/HH) - mu*mu;
    float rstd = rsqrtf(var + 1e-5f);
    float* zb = g_z + (size_t)b*HH*LL + l;
    #pragma unroll 8
    for (int h = 0; h < HH; h++) {
        float v = xb[(size_t)h*LL] + tbs[h];
        zb[(size_t)h*LL] = (v - mu)*rstd*gs[h] + bs[h];
    }
}

// ---------------- scan: one warp per (b,h), fwd+bwd chains simultaneously ----------------
#define SCAN_WPB 4
__global__ __launch_bounds__(32*SCAN_WPB) void k_scan(const float* __restrict__ Dv)
{
    __shared__ __align__(16) float pwf_s[SCAN_WPB][16*33];
    __shared__ __align__(16) float pwb_s[SCAN_WPB][16*33];
    int wid  = threadIdx.x >> 5;
    int lane = threadIdx.x & 31;
    int bh   = blockIdx.x*SCAN_WPB + wid;
    int h    = bh & (HH-1);
    int ci   = h*NS + lane;
    float* pwf = pwf_s[wid];
    float* pwb = pwb_s[wid];

    u64 wr2   = pk2(g_wr[ci],   g_wr[ci+32]);
    u64 wi2   = pk2(g_wi[ci],   g_wi[ci+32]);
    u64 wi2n  = pk2(-g_wi[ci],  -g_wi[ci+32]);
    u64 c0r2  = pk2(g_c0r[ci],  g_c0r[ci+32]);
    u64 c0i2n = pk2(-g_c0i[ci], -g_c0i[ci+32]);
    u64 c1r2  = pk2(g_c1r[ci],  g_c1r[ci+32]);
    u64 c1i2n = pk2(-g_c1i[ci], -g_c1i[ci+32]);
    float d = Dv[h];

    const float* zp  = g_z  + (size_t)bh*LL;
    float*       yfp = g_yf + (size_t)bh*LL;
    float*       ybp = g_yb + (size_t)bh*LL;

    u64 fsr = 0ULL, fsi = 0ULL, bsr = 0ULL, bsi = 0ULL;
    const int row = lane & 15;
    const int k0  = (lane >> 4) * 16;

    for (int t = 0; t < LL/32; t++) {
        int l0f = t*32;
        int l0b = LL - 32*(t+1);
        float zvf = zp[l0f + lane];
        float zvb = zp[l0b + lane];

        // ---- chunk 0: fwd j = 0..15 ; bwd jr = 31..16 ----
        #pragma unroll
        for (int jj = 0; jj < 16; jj++) {
            int jf = jj, jr = 31 - jj;
            float zf = __shfl_sync(0xffffffffu, zvf, jf);
            u64 zf2 = pk2(zf, zf);
            u64 nfr = fma2(wr2, fsr, fma2(wi2n, fsi, zf2));
            fsi = fma2(wr2, fsi, mul2(wi2, fsr));
            fsr = nfr;
            u64 pf = fma2(c0r2, fsr, mul2(c0i2n, fsi));
            float pa, pb; up2(pf, pa, pb);
            pwf[jf*33 + lane] = pa + pb;

            // bwd: emit from state BEFORE absorbing z[jr]
            u64 pv = fma2(c1r2, bsr, mul2(c1i2n, bsi));
            float qa, qb; up2(pv, qa, qb);
            pwb[(jr-16)*33 + lane] = qa + qb;
            float zb = __shfl_sync(0xffffffffu, zvb, jr);
            u64 zb2 = pk2(zb, zb);
            u64 nbr = fma2(wr2, bsr, fma2(wi2n, bsi, zb2));
            bsi = fma2(wr2, bsi, mul2(wi2, bsr));
            bsr = nbr;
        }
        __syncwarp();
        {
            float af = 0.f, ab = 0.f;
            #pragma unroll
            for (int k = 0; k < 16; k++) {
                af += pwf[row*33 + k0 + k];
                ab += pwb[row*33 + k0 + k];
            }
            af += __shfl_xor_sync(0xffffffffu, af, 16);
            ab += __shfl_xor_sync(0xffffffffu, ab, 16);
            float zsh = __shfl_sync(0xffffffffu, zvb, 16 + row);
            if (lane < 16) {
                yfp[l0f + row]      = af;
                ybp[l0b + 16 + row] = ab + d*zsh;
            }
        }
        __syncwarp();

        // ---- chunk 1: fwd j = 16..31 ; bwd jr = 15..0 ----
        #pragma unroll
        for (int jj = 0; jj < 16; jj++) {
            int jf = 16 + jj, jr = 15 - jj;
            float zf = __shfl_sync(0xffffffffu, zvf, jf);
            u64 zf2 = pk2(zf, zf);
            u64 nfr = fma2(wr2, fsr, fma2(wi2n, fsi, zf2));
            fsi = fma2(wr2, fsi, mul2(wi2, fsr));
            fsr = nfr;
            u64 pf = fma2(c0r2, fsr, mul2(c0i2n, fsi));
            float pa, pb; up2(pf, pa, pb);
            pwf[(jf-16)*33 + lane] = pa + pb;

            u64 pv = fma2(c1r2, bsr, mul2(c1i2n, bsi));
            float qa, qb; up2(pv, qa, qb);
            pwb[jr*33 + lane] = qa + qb;
            float zb = __shfl_sync(0xffffffffu, zvb, jr);
            u64 zb2 = pk2(zb, zb);
            u64 nbr = fma2(wr2, bsr, fma2(wi2n, bsi, zb2));
            bsi = fma2(wr2, bsi, mul2(wi2, bsr));
            bsr = nbr;
        }
        __syncwarp();
        {
            float af = 0.f, ab = 0.f;
            #pragma unroll
            for (int k = 0; k < 16; k++) {
                af += pwf[row*33 + k0 + k];
                ab += pwb[row*33 + k0 + k];
            }
            af += __shfl_xor_sync(0xffffffffu, af, 16);
            ab += __shfl_xor_sync(0xffffffffu, ab, 16);
            float zsh = __shfl_sync(0xffffffffu, zvb, row);
            if (lane < 16) {
                yfp[l0f + 16 + row] = af;
                ybp[l0b + row]      = ab + d*zsh;
            }
        }
        __syncwarp();
    }
}

// ---------------- y = gelu(yf + yb') -> g_yf ----------------
__global__ void k_gelu()
{
    int i = blockIdx.x*256 + threadIdx.x;
    float y = g_yf[i] + g_yb[i];
    float u = 0.7978845608028654f * fmaf(0.044715f*y, y*y, y);
    float e = __expf(fminf(-2.f*u, 80.f));
    float th = (1.f - e) / (1.f + e);
    g_yf[i] = 0.5f*y*(1.f + th);
}

// ---------------- stage1: 128x128 tile, 8x8 thread tile ----------------
__global__ __launch_bounds__(256) void k_stage1(const float* __restrict__ Wout, const float* __restrict__ bout,
                         const float* __restrict__ x, const float* __restrict__ feat,
                         const float* __restrict__ Wf, const float* __restrict__ bf)
{
    __shared__ __align__(16) float Ws[16][130];
    __shared__ __align__(16) float Bs[16][129];
    const int b  = blockIdx.z;
    const int g0 = blockIdx.y * 128;
    const int l0 = blockIdx.x * 128;
    const int tid = threadIdx.x;
    const int tx = tid & 15, ty = tid >> 4;
    const int arow = tid >> 1, akg = (tid & 1) * 8;
    const int brow = tid >> 4, bc0 = tid & 15;

    u64 acc[4][8];
    #pragma unroll
    for (int r = 0; r < 4; r++)
        #pragma unroll
        for (int j = 0; j < 8; j++) acc[r][j] = 0ULL;

    const float* act = g_yf + (size_t)b*HH*LL;
    for (int k0 = 0; k0 < HH; k0 += 16) {
        float4 w0 = *(const float4*)(Wout + (size_t)(g0+arow)*HH + k0 + akg);
        float4 w1 = *(const float4*)(Wout + (size_t)(g0+arow)*HH + k0 + akg + 4);
        Ws[akg+0][arow]=w0.x; Ws[akg+1][arow]=w0.y; Ws[akg+2][arow]=w0.z; Ws[akg+3][arow]=w0.w;
        Ws[akg+4][arow]=w1.x; Ws[akg+5][arow]=w1.y; Ws[akg+6][arow]=w1.z; Ws[akg+7][arow]=w1.w;
        #pragma unroll
        for (int c = 0; c < 8; c++)
            Bs[brow][bc0 + 16*c] = act[(size_t)(k0+brow)*LL + l0 + bc0 + 16*c];
        __syncthreads();
        #pragma unroll
        for (int k = 0; k < 16; k++) {
            u64 ap[4], bp[8];
            #pragma unroll
            for (int r = 0; r < 4; r++) ap[r] = *(const u64*)&Ws[k][ty*8 + 2*r];
            #pragma unroll
            for (int j = 0; j < 8; j++) { float v = Bs[k][16*j + tx]; bp[j] = pk2(v, v); }
            #pragma unroll
            for (int r = 0; r < 4; r++)
                #pragma unroll
                for (int j = 0; j < 8; j++)
                    acc[r][j] = fma2(ap[r], bp[j], acc[r][j]);
        }
        __syncthreads();
    }
    const float* fb = feat + (size_t)b*FF*LL;
    for (int k0 = 0; k0 < FF; k0 += 16) {
        float4 w0 = *(const float4*)(Wf + (size_t)(g0+arow)*FF + k0 + akg);
        float4 w1 = *(const float4*)(Wf + (size_t)(g0+arow)*FF + k0 + akg + 4);
        Ws[akg+0][arow]=w0.x; Ws[akg+1][arow]=w0.y; Ws[akg+2][arow]=w0.z; Ws[akg+3][arow]=w0.w;
        Ws[akg+4][arow]=w1.x; Ws[akg+5][arow]=w1.y; Ws[akg+6][arow]=w1.z; Ws[akg+7][arow]=w1.w;
        #pragma unroll
        for (int c = 0; c < 8; c++)
            Bs[brow][bc0 + 16*c] = fb[(size_t)(k0+brow)*LL + l0 + bc0 + 16*c];
        __syncthreads();
        #pragma unroll
        for (int k = 0; k < 16; k++) {
            u64 ap[4], bp[8];
            #pragma unroll
            for (int r = 0; r < 4; r++) ap[r] = *(const u64*)&Ws[k][ty*8 + 2*r];
            #pragma unroll
            for (int j = 0; j < 8; j++) { float v = Bs[k][16*j + tx]; bp[j] = pk2(v, v); }
            #pragma unroll
            for (int r = 0; r < 4; r++)
                #pragma unroll
                for (int j = 0; j < 8; j++)
                    acc[r][j] = fma2(ap[r], bp[j], acc[r][j]);
        }
        __syncthreads();
    }
    float base[8];
    #pragma unroll
    for (int i = 0; i < 8; i++) {
        int g = g0 + ty*8 + i;
        base[i] = bout[g] + bf[g] + g_tb[b*HH + g];
    }
    #pragma unroll
    for (int r = 0; r < 4; r++) {
        int g = g0 + ty*8 + 2*r;
        #pragma unroll
        for (int j = 0; j < 8; j++) {
            float v0, v1; up2(acc[r][j], v0, v1);
            int col = l0 + 16*j + tx;
            size_t off0 = ((size_t)b*HH + g)*LL + col;
            size_t off1 = off0 + LL;
            float o0 = v0 + base[2*r]   + x[off0];
            float o1 = v1 + base[2*r+1] + x[off1];
            g_z[off0] = gatef(o0);
            g_z[off1] = gatef(o1);
        }
    }
}

// ---------------- stage2: o1 = W1@g + b1 + x ; o2 = W2@g + b2 ----------------
__global__ __launch_bounds__(256) void k_stage2(const float* __restrict__ W1, const float* __restrict__ b1,
                         const float* __restrict__ W2, const float* __restrict__ b2,
                         const float* __restrict__ x, float* __restrict__ o1,
                         float* __restrict__ o2)
{
    __shared__ __align__(16) float W1s[16][130];
    __shared__ __align__(16) float W2s[16][130];
    __shared__ __align__(16) float Bs[16][65];
    const int b  = blockIdx.z;
    const int g0 = blockIdx.y * 128;
    const int l0 = blockIdx.x * 64;
    const int tid = threadIdx.x;
    const int tx = tid & 15, ty = tid >> 4;
    const int arow = tid >> 1, akg = (tid & 1) * 8;
    const int brow = tid >> 4, bc0 = tid & 15;

    u64 acc1[4][4], acc2[4][4];
    #pragma unroll
    for (int r = 0; r < 4; r++)
        #pragma unroll
        for (int j = 0; j < 4; j++) { acc1[r][j] = 0ULL; acc2[r][j] = 0ULL; }

    const float* gb = g_z + (size_t)b*HH*LL;
    for (int k0 = 0; k0 < HH; k0 += 16) {
        float4 w0 = *(const float4*)(W1 + (size_t)(g0+arow)*HH + k0 + akg);
        float4 w1 = *(const float4*)(W1 + (size_t)(g0+arow)*HH + k0 + akg + 4);
        W1s[akg+0][arow]=w0.x; W1s[akg+1][arow]=w0.y; W1s[akg+2][arow]=w0.z; W1s[akg+3][arow]=w0.w;
        W1s[akg+4][arow]=w1.x; W1s[akg+5][arow]=w1.y; W1s[akg+6][arow]=w1.z; W1s[akg+7][arow]=w1.w;
        float4 v0 = *(const float4*)(W2 + (size_t)(g0+arow)*HH + k0 + akg);
        float4 v1 = *(const float4*)(W2 + (size_t)(g0+arow)*HH + k0 + akg + 4);
        W2s[akg+0][arow]=v0.x; W2s[akg+1][arow]=v0.y; W2s[akg+2][arow]=v0.z; W2s[akg+3][arow]=v0.w;
        W2s[akg+4][arow]=v1.x; W2s[akg+5][arow]=v1.y; W2s[akg+6][arow]=v1.z; W2s[akg+7][arow]=v1.w;
        #pragma unroll
        for (int c = 0; c < 4; c++)
            Bs[brow][bc0 + 16*c] = gb[(size_t)(k0+brow)*LL + l0 + bc0 + 16*c];
        __syncthreads();
        #pragma unroll
        for (int k = 0; k < 16; k++) {
            u64 a1[4], a2[4], bp[4];
            #pragma unroll
            for (int r = 0; r < 4; r++) a1[r] = *(const u64*)&W1s[k][ty*8 + 2*r];
            #pragma unroll
            for (int r = 0; r < 4; r++) a2[r] = *(const u64*)&W2s[k][ty*8 + 2*r];
            #pragma unroll
            for (int j = 0; j < 4; j++) { float v = Bs[k][16*j + tx]; bp[j] = pk2(v, v); }
            #pragma unroll
            for (int r = 0; r < 4; r++)
                #pragma unroll
                for (int j = 0; j < 4; j++) {
                    acc1[r][j] = fma2(a1[r], bp[j], acc1[r][j]);
                    acc2[r][j] = fma2(a2[r], bp[j], acc2[r][j]);
                }
        }
        __syncthreads();
    }
    #pragma unroll
    for (int r = 0; r < 4; r++) {
        int g = g0 + ty*8 + 2*r;
        float bb1a = b1[g], bb1b = b1[g+1];
        float bb2a = b2[g], bb2b = b2[g+1];
        #pragma unroll
        for (int j = 0; j < 4; j++) {
            int col = l0 + 16*j + tx;
            size_t off0 = ((size_t)b*HH + g)*LL + col;
            size_t off1 = off0 + LL;
            float p0, p1, q0, q1;
            up2(acc1[r][j], p0, p1);
            up2(acc2[r][j], q0, q1);
            o1[off0] = p0 + bb1a + x[off0];
            o1[off1] = p1 + bb1b + x[off1];
            o2[off0] = q0 + bb2a;
            o2[off1] = q1 + bb2b;
        }
    }
}

// ---------------- launch ----------------
extern "C" void kernel_launch(void* const* d_in, const int* in_sizes, int n_in,
                              void* d_out, int out_size)
{
    const float* x        = (const float*)d_in[0];
    const float* t        = (const float*)d_in[1];
    const float* feat     = (const float*)d_in[2];
    const float* Wt       = (const float*)d_in[3];
    const float* bt       = (const float*)d_in[4];
    const float* ln_g     = (const float*)d_in[5];
    const float* ln_b     = (const float*)d_in[6];
    const float* log_dt   = (const float*)d_in[7];
    const float* logA_real= (const float*)d_in[8];
    const float* A_imag   = (const float*)d_in[9];
    const float* C_re     = (const float*)d_in[10];
    const float* C_im     = (const float*)d_in[11];
    const float* Dv       = (const float*)d_in[12];
    const float* Wout     = (const float*)d_in[13];
    const float* bout     = (const float*)d_in[14];
    const float* W1       = (const float*)d_in[15];
    const float* b1       = (const float*)d_in[16];
    const float* W2       = (const float*)d_in[17];
    const float* b2       = (const float*)d_in[18];
    const float* Wf       = (const float*)d_in[19];
    const float* bf       = (const float*)d_in[20];

    float* o1 = (float*)d_out;
    float* o2 = (float*)d_out + (size_t)BHL;

    k_tb<<<BB, 256>>>(t, Wt, bt);
    k_ssm<<<(HH*NS+255)/256, 256>>>(log_dt, logA_real, A_imag, C_re, C_im);
    k_ln<<<dim3(LL/256, BB), 256>>>(x, ln_g, ln_b);
    k_scan<<<(BB*HH)/SCAN_WPB, 32*SCAN_WPB>>>(Dv);
    k_gelu<<<BHL/256, 256>>>();
    k_stage1<<<dim3(LL/128, HH/128, BB), 256>>>(Wout, bout, x, feat, Wf, bf);
    k_stage2<<<dim3(LL/64, HH/128, BB), 256>>>(W1, b1, W2, b2, x, o1, o2);
}

// round 7
// speedup vs baseline: 1.0323x; 1.0323x over previous
#include <cuda_runtime.h>
#include <math.h>

#define BB 32
#define HH 256
#define LL 2048
#define NS 64
#define FF 32
#define BHL (BB*HH*LL)

typedef unsigned long long u64;

// ---------------- f32x2 helpers ----------------
__device__ __forceinline__ u64 pk2(float lo, float hi) {
    u64 r; asm("mov.b64 %0, {%1, %2};" : "=l"(r) : "f"(lo), "f"(hi)); return r;
}
__device__ __forceinline__ void up2(u64 v, float& a, float& b) {
    asm("mov.b64 {%0, %1}, %2;" : "=f"(a), "=f"(b) : "l"(v));
}
__device__ __forceinline__ u64 fma2(u64 a, u64 b, u64 c) {
    u64 d; asm("fma.rn.f32x2 %0, %1, %2, %3;" : "=l"(d) : "l"(a), "l"(b), "l"(c)); return d;
}
__device__ __forceinline__ u64 mul2(u64 a, u64 b) {
    u64 d; asm("mul.rn.f32x2 %0, %1, %2;" : "=l"(d) : "l"(a), "l"(b)); return d;
}

__device__ __forceinline__ float gatef(float o) {
    float u = __expf(fminf(-o, 25.f));
    float u2 = u * u;
    return (1.f - u2) / ((1.f + u2) * (1.f + u));
}

// ---------------- scratch ----------------
__device__ float g_tb[BB*HH];
__device__ float g_wr[HH*NS], g_wi[HH*NS];
__device__ float g_c0r[HH*NS], g_c0i[HH*NS], g_c1r[HH*NS], g_c1i[HH*NS];
__device__ float g_z [BHL];
__device__ float g_yf[BHL];
__device__ float g_yb[BHL];   // holds yb + D*z

// ---------------- t @ Wt^T + bt ----------------
__global__ void k_tb(const float* __restrict__ t, const float* __restrict__ Wt,
                     const float* __restrict__ bt)
{
    __shared__ float ts[HH];
    int b = blockIdx.x, h = threadIdx.x;
    ts[h] = t[b*HH + h];
    __syncthreads();
    float acc = bt[h];
    const float* wrow = Wt + (size_t)h*HH;
    #pragma unroll 8
    for (int k = 0; k < HH; k++) acc = fmaf(ts[k], wrow[k], acc);
    g_tb[b*HH + h] = acc;
}

// ---------------- SSM parameter prep ----------------
__global__ void k_ssm(const float* __restrict__ log_dt, const float* __restrict__ logA_real,
                      const float* __restrict__ A_imag, const float* __restrict__ C_re,
                      const float* __restrict__ C_im)
{
    int i = blockIdx.x*blockDim.x + threadIdx.x;
    if (i >= HH*NS) return;
    int h = i / NS;
    float dt = expf(log_dt[h]);
    float Ar = -expf(logA_real[i]);
    float Ai = A_imag[i];
    float dr = dt*Ar, di = dt*Ai;
    float er = expf(dr);
    float wr = er*cosf(di), wi = er*sinf(di);
    g_wr[i] = wr; g_wi[i] = wi;
    float Er = wr - 1.0f, Ei = wi;
    float inv = 1.0f/(Ar*Ar + Ai*Ai);
    float qr = (Er*Ar + Ei*Ai)*inv;
    float qi = (Ei*Ar - Er*Ai)*inv;
    {
        float cr = C_re[i], ci = C_im[i];
        g_c0r[i] = 2.0f*(cr*qr - ci*qi);
        g_c0i[i] = 2.0f*(cr*qi + ci*qr);
    }
    {
        float cr = C_re[HH*NS + i], ci = C_im[HH*NS + i];
        g_c1r[i] = 2.0f*(cr*qr - ci*qi);
        g_c1i[i] = 2.0f*(cr*qi + ci*qr);
    }
}

// ---------------- LayerNorm over H -> z ----------------
__global__ void k_ln(const float* __restrict__ x, const float* __restrict__ ln_g,
                     const float* __restrict__ ln_b)
{
    __shared__ float tbs[HH], gs[HH], bs[HH];
    int b = blockIdx.y;
    int l = blockIdx.x*256 + threadIdx.x;
    tbs[threadIdx.x] = g_tb[b*HH + threadIdx.x];
    gs[threadIdx.x]  = ln_g[threadIdx.x];
    bs[threadIdx.x]  = ln_b[threadIdx.x];
    __syncthreads();
    const float* xb = x + (size_t)b*HH*LL + l;
    float s = 0.f, ss = 0.f;
    #pragma unroll 8
    for (int h = 0; h < HH; h++) {
        float v = xb[(size_t)h*LL] + tbs[h];
        s += v; ss = fmaf(v, v, ss);
    }
    float mu  = s * (1.0f/HH);
    float var = ss*(1.0f/HH) - mu*mu;
    float rstd = rsqrtf(var + 1e-5f);
    float* zb = g_z + (size_t)b*HH*LL + l;
    #pragma unroll 8
    for (int h = 0; h < HH; h++) {
        float v = xb[(size_t)h*LL] + tbs[h];
        zb[(size_t)h*LL] = (v - mu)*rstd*gs[h] + bs[h];
    }
}

// ---------------- scan: one warp per (b,h,dir), shfl z-broadcast, scalar transpose ----------------
#define SCAN_WPB 4
__global__ __launch_bounds__(32*SCAN_WPB) void k_scan(const float* __restrict__ Dv)
{
    __shared__ __align__(16) float pbuf[SCAN_WPB][32*33];
    int wid  = threadIdx.x >> 5;
    int lane = threadIdx.x & 31;
    int gw   = blockIdx.x*SCAN_WPB + wid;   // 0 .. 2*B*H-1
    int bh   = gw >> 1;
    int dir  = gw & 1;
    int h    = bh & (HH-1);
    int ci   = h*NS + lane;
    float* pw = pbuf[wid];

    u64 wr2  = pk2(g_wr[ci],  g_wr[ci+32]);
    u64 wi2  = pk2(g_wi[ci],  g_wi[ci+32]);
    u64 wi2n = pk2(-g_wi[ci], -g_wi[ci+32]);
    u64 cr2, ci2n;
    if (dir == 0) { cr2 = pk2(g_c0r[ci], g_c0r[ci+32]); ci2n = pk2(-g_c0i[ci], -g_c0i[ci+32]); }
    else          { cr2 = pk2(g_c1r[ci], g_c1r[ci+32]); ci2n = pk2(-g_c1i[ci], -g_c1i[ci+32]); }

    const float* zp = g_z + (size_t)bh*LL;
    float* yp = (dir == 0 ? g_yf : g_yb) + (size_t)bh*LL;

    u64 sr = 0ULL, si = 0ULL;

    if (dir == 0) {
        for (int t = 0; t < LL/32; t++) {
            int l0 = t*32;
            float zv = zp[l0 + lane];
            #pragma unroll
            for (int j = 0; j < 32; j++) {
                float zl = __shfl_sync(0xffffffffu, zv, j);
                u64 z2 = pk2(zl, zl);
                u64 nsr = fma2(wr2, sr, fma2(wi2n, si, z2));
                si = fma2(wr2, si, mul2(wi2, sr));
                sr = nsr;
                u64 p2 = fma2(cr2, sr, mul2(ci2n, si));
                float pa, pb; up2(p2, pa, pb);
                pw[j*33 + lane] = pa + pb;
            }
            __syncwarp();
            float acc = 0.f;
            #pragma unroll
            for (int k = 0; k < 32; k++) acc += pw[lane*33 + k];
            yp[l0 + lane] = acc;
            __syncwarp();
        }
    } else {
        float d = Dv[h];
        for (int t = 0; t < LL/32; t++) {
            int l0 = LL - 32*(t+1);
            float zv = zp[l0 + lane];
            #pragma unroll
            for (int j = 31; j >= 0; j--) {
                // emit contribution from state BEFORE absorbing z[l0+j]
                u64 p2 = fma2(cr2, sr, mul2(ci2n, si));
                float pa, pb; up2(p2, pa, pb);
                pw[j*33 + lane] = pa + pb;
                float zl = __shfl_sync(0xffffffffu, zv, j);
                u64 z2 = pk2(zl, zl);
                u64 nsr = fma2(wr2, sr, fma2(wi2n, si, z2));
                si = fma2(wr2, si, mul2(wi2, sr));
                sr = nsr;
            }
            __syncwarp();
            float acc = 0.f;
            #pragma unroll
            for (int k = 0; k < 32; k++) acc += pw[lane*33 + k];
            yp[l0 + lane] = fmaf(d, zv, acc);   // fold D*z into bwd output
            __syncwarp();
        }
    }
}

// ---------------- y = gelu(yf + yb') -> g_yf (float4) ----------------
__global__ void k_gelu()
{
    int i = (blockIdx.x*256 + threadIdx.x) * 4;
    float4 a = *(const float4*)(g_yf + i);
    float4 b = *(const float4*)(g_yb + i);
    float y[4] = {a.x+b.x, a.y+b.y, a.z+b.z, a.w+b.w};
    float4 o;
    float* op = &o.x;
    #pragma unroll
    for (int k = 0; k < 4; k++) {
        float u = 0.7978845608028654f * fmaf(0.044715f*y[k], y[k]*y[k], y[k]);
        float e = __expf(fminf(-2.f*u, 80.f));
        float th = (1.f - e) / (1.f + e);
        op[k] = 0.5f*y[k]*(1.f + th);
    }
    *(float4*)(g_yf + i) = o;
}

// ---------------- stage1: 128x64 tile ----------------
__global__ __launch_bounds__(256) void k_stage1(const float* __restrict__ Wout, const float* __restrict__ bout,
                         const float* __restrict__ x, const float* __restrict__ feat,
                         const float* __restrict__ Wf, const float* __restrict__ bf)
{
    __shared__ __align__(16) float Ws[16][130];
    __shared__ __align__(16) float Bs[16][65];
    const int b  = blockIdx.z;
    const int g0 = blockIdx.y * 128;
    const int l0 = blockIdx.x * 64;
    const int tid = threadIdx.x;
    const int tx = tid & 15, ty = tid >> 4;
    const int arow = tid >> 1, akg = (tid & 1) * 8;
    const int brow = tid >> 4, bc0 = tid & 15;

    u64 acc[4][4];
    #pragma unroll
    for (int r = 0; r < 4; r++)
        #pragma unroll
        for (int j = 0; j < 4; j++) acc[r][j] = 0ULL;

    const float* act = g_yf + (size_t)b*HH*LL;
    for (int k0 = 0; k0 < HH; k0 += 16) {
        float4 w0 = *(const float4*)(Wout + (size_t)(g0+arow)*HH + k0 + akg);
        float4 w1 = *(const float4*)(Wout + (size_t)(g0+arow)*HH + k0 + akg + 4);
        Ws[akg+0][arow]=w0.x; Ws[akg+1][arow]=w0.y; Ws[akg+2][arow]=w0.z; Ws[akg+3][arow]=w0.w;
        Ws[akg+4][arow]=w1.x; Ws[akg+5][arow]=w1.y; Ws[akg+6][arow]=w1.z; Ws[akg+7][arow]=w1.w;
        #pragma unroll
        for (int c = 0; c < 4; c++)
            Bs[brow][bc0 + 16*c] = act[(size_t)(k0+brow)*LL + l0 + bc0 + 16*c];
        __syncthreads();
        #pragma unroll
        for (int k = 0; k < 16; k++) {
            u64 ap[4], bp[4];
            #pragma unroll
            for (int r = 0; r < 4; r++) ap[r] = *(const u64*)&Ws[k][ty*8 + 2*r];
            #pragma unroll
            for (int j = 0; j < 4; j++) { float v = Bs[k][16*j + tx]; bp[j] = pk2(v, v); }
            #pragma unroll
            for (int r = 0; r < 4; r++)
                #pragma unroll
                for (int j = 0; j < 4; j++)
                    acc[r][j] = fma2(ap[r], bp[j], acc[r][j]);
        }
        __syncthreads();
    }
    const float* fb = feat + (size_t)b*FF*LL;
    for (int k0 = 0; k0 < FF; k0 += 16) {
        float4 w0 = *(const float4*)(Wf + (size_t)(g0+arow)*FF + k0 + akg);
        float4 w1 = *(const float4*)(Wf + (size_t)(g0+arow)*FF + k0 + akg + 4);
        Ws[akg+0][arow]=w0.x; Ws[akg+1][arow]=w0.y; Ws[akg+2][arow]=w0.z; Ws[akg+3][arow]=w0.w;
        Ws[akg+4][arow]=w1.x; Ws[akg+5][arow]=w1.y; Ws[akg+6][arow]=w1.z; Ws[akg+7][arow]=w1.w;
        #pragma unroll
        for (int c = 0; c < 4; c++)
            Bs[brow][bc0 + 16*c] = fb[(size_t)(k0+brow)*LL + l0 + bc0 + 16*c];
        __syncthreads();
        #pragma unroll
        for (int k = 0; k < 16; k++) {
            u64 ap[4], bp[4];
            #pragma unroll
            for (int r = 0; r < 4; r++) ap[r] = *(const u64*)&Ws[k][ty*8 + 2*r];
            #pragma unroll
            for (int j = 0; j < 4; j++) { float v = Bs[k][16*j + tx]; bp[j] = pk2(v, v); }
            #pragma unroll
            for (int r = 0; r < 4; r++)
                #pragma unroll
                for (int j = 0; j < 4; j++)
                    acc[r][j] = fma2(ap[r], bp[j], acc[r][j]);
        }
        __syncthreads();
    }
    float base[8];
    #pragma unroll
    for (int i = 0; i < 8; i++) {
        int g = g0 + ty*8 + i;
        base[i] = bout[g] + bf[g] + g_tb[b*HH + g];
    }
    #pragma unroll
    for (int r = 0; r < 4; r++) {
        int g = g0 + ty*8 + 2*r;
        #pragma unroll
        for (int j = 0; j < 4; j++) {
            float v0, v1; up2(acc[r][j], v0, v1);
            int col = l0 + 16*j + tx;
            size_t off0 = ((size_t)b*HH + g)*LL + col;
            size_t off1 = off0 + LL;
            float o0 = v0 + base[2*r]   + x[off0];
            float o1 = v1 + base[2*r+1] + x[off1];
            g_z[off0] = gatef(o0);
            g_z[off1] = gatef(o1);
        }
    }
}

// ---------------- stage2: o1 = W1@g + b1 + x ; o2 = W2@g + b2 ----------------
__global__ __launch_bounds__(256) void k_stage2(const float* __restrict__ W1, const float* __restrict__ b1,
                         const float* __restrict__ W2, const float* __restrict__ b2,
                         const float* __restrict__ x, float* __restrict__ o1,
                         float* __restrict__ o2)
{
    __shared__ __align__(16) float W1s[16][130];
    __shared__ __align__(16) float W2s[16][130];
    __shared__ __align__(16) float Bs[16][65];
    const int b  = blockIdx.z;
    const int g0 = blockIdx.y * 128;
    const int l0 = blockIdx.x * 64;
    const int tid = threadIdx.x;
    const int tx = tid & 15, ty = tid >> 4;
    const int arow = tid >> 1, akg = (tid & 1) * 8;
    const int brow = tid >> 4, bc0 = tid & 15;

    u64 acc1[4][4], acc2[4][4];
    #pragma unroll
    for (int r = 0; r < 4; r++)
        #pragma unroll
        for (int j = 0; j < 4; j++) { acc1[r][j] = 0ULL; acc2[r][j] = 0ULL; }

    const float* gb = g_z + (size_t)b*HH*LL;
    for (int k0 = 0; k0 < HH; k0 += 16) {
        float4 w0 = *(const float4*)(W1 + (size_t)(g0+arow)*HH + k0 + akg);
        float4 w1 = *(const float4*)(W1 + (size_t)(g0+arow)*HH + k0 + akg + 4);
        W1s[akg+0][arow]=w0.x; W1s[akg+1][arow]=w0.y; W1s[akg+2][arow]=w0.z; W1s[akg+3][arow]=w0.w;
        W1s[akg+4][arow]=w1.x; W1s[akg+5][arow]=w1.y; W1s[akg+6][arow]=w1.z; W1s[akg+7][arow]=w1.w;
        float4 v0 = *(const float4*)(W2 + (size_t)(g0+arow)*HH + k0 + akg);
        float4 v1 = *(const float4*)(W2 + (size_t)(g0+arow)*HH + k0 + akg + 4);
        W2s[akg+0][arow]=v0.x; W2s[akg+1][arow]=v0.y; W2s[akg+2][arow]=v0.z; W2s[akg+3][arow]=v0.w;
        W2s[akg+4][arow]=v1.x; W2s[akg+5][arow]=v1.y; W2s[akg+6][arow]=v1.z; W2s[akg+7][arow]=v1.w;
        #pragma unroll
        for (int c = 0; c < 4; c++)
            Bs[brow][bc0 + 16*c] = gb[(size_t)(k0+brow)*LL + l0 + bc0 + 16*c];
        __syncthreads();
        #pragma unroll
        for (int k = 0; k < 16; k++) {
            u64 a1[4], a2[4], bp[4];
            #pragma unroll
            for (int r = 0; r < 4; r++) a1[r] = *(const u64*)&W1s[k][ty*8 + 2*r];
            #pragma unroll
            for (int r = 0; r < 4; r++) a2[r] = *(const u64*)&W2s[k][ty*8 + 2*r];
            #pragma unroll
            for (int j = 0; j < 4; j++) { float v = Bs[k][16*j + tx]; bp[j] = pk2(v, v); }
            #pragma unroll
            for (int r = 0; r < 4; r++)
                #pragma unroll
                for (int j = 0; j < 4; j++) {
                    acc1[r][j] = fma2(a1[r], bp[j], acc1[r][j]);
                    acc2[r][j] = fma2(a2[r], bp[j], acc2[r][j]);
                }
        }
        __syncthreads();
    }
    #pragma unroll
    for (int r = 0; r < 4; r++) {
        int g = g0 + ty*8 + 2*r;
        float bb1a = b1[g], bb1b = b1[g+1];
        float bb2a = b2[g], bb2b = b2[g+1];
        #pragma unroll
        for (int j = 0; j < 4; j++) {
            int col = l0 + 16*j + tx;
            size_t off0 = ((size_t)b*HH + g)*LL + col;
            size_t off1 = off0 + LL;
            float p0, p1, q0, q1;
            up2(acc1[r][j], p0, p1);
            up2(acc2[r][j], q0, q1);
            o1[off0] = p0 + bb1a + x[off0];
            o1[off1] = p1 + bb1b + x[off1];
            o2[off0] = q0 + bb2a;
            o2[off1] = q1 + bb2b;
        }
    }
}

// ---------------- launch ----------------
extern "C" void kernel_launch(void* const* d_in, const int* in_sizes, int n_in,
                              void* d_out, int out_size)
{
    const float* x        = (const float*)d_in[0];
    const float* t        = (const float*)d_in[1];
    const float* feat     = (const float*)d_in[2];
    const float* Wt       = (const float*)d_in[3];
    const float* bt       = (const float*)d_in[4];
    const float* ln_g     = (const float*)d_in[5];
    const float* ln_b     = (const float*)d_in[6];
    const float* log_dt   = (const float*)d_in[7];
    const float* logA_real= (const float*)d_in[8];
    const float* A_imag   = (const float*)d_in[9];
    const float* C_re     = (const float*)d_in[10];
    const float* C_im     = (const float*)d_in[11];
    const float* Dv       = (const float*)d_in[12];
    const float* Wout     = (const float*)d_in[13];
    const float* bout     = (const float*)d_in[14];
    const float* W1       = (const float*)d_in[15];
    const float* b1       = (const float*)d_in[16];
    const float* W2       = (const float*)d_in[17];
    const float* b2       = (const float*)d_in[18];
    const float* Wf       = (const float*)d_in[19];
    const float* bf       = (const float*)d_in[20];

    float* o1 = (float*)d_out;
    float* o2 = (float*)d_out + (size_t)BHL;

    k_tb<<<BB, 256>>>(t, Wt, bt);
    k_ssm<<<(HH*NS+255)/256, 256>>>(log_dt, logA_real, A_imag, C_re, C_im);
    k_ln<<<dim3(LL/256, BB), 256>>>(x, ln_g, ln_b);
    k_scan<<<(2*BB*HH)/SCAN_WPB, 32*SCAN_WPB>>>(Dv);
    k_gelu<<<BHL/1024, 256>>>();
    k_stage1<<<dim3(LL/64, HH/128, BB), 256>>>(Wout, bout, x, feat, Wf, bf);
    k_stage2<<<dim3(LL/64, HH/128, BB), 256>>>(W1, b1, W2, b2, x, o1, o2);
}

// round 8
// speedup vs baseline: 1.0808x; 1.0469x over previous
#include <cuda_runtime.h>
#include <math.h>

#define BB 32
#define HH 256
#define LL 2048
#define NS 64
#define FF 32
#define BHL (BB*HH*LL)

typedef unsigned long long u64;

// ---------------- f32x2 helpers ----------------
__device__ __forceinline__ u64 pk2(float lo, float hi) {
    u64 r; asm("mov.b64 %0, {%1, %2};" : "=l"(r) : "f"(lo), "f"(hi)); return r;
}
__device__ __forceinline__ void up2(u64 v, float& a, float& b) {
    asm("mov.b64 {%0, %1}, %2;" : "=f"(a), "=f"(b) : "l"(v));
}
__device__ __forceinline__ u64 fma2(u64 a, u64 b, u64 c) {
    u64 d; asm("fma.rn.f32x2 %0, %1, %2, %3;" : "=l"(d) : "l"(a), "l"(b), "l"(c)); return d;
}
__device__ __forceinline__ u64 mul2(u64 a, u64 b) {
    u64 d; asm("mul.rn.f32x2 %0, %1, %2;" : "=l"(d) : "l"(a), "l"(b)); return d;
}

__device__ __forceinline__ float gatef(float o) {
    float u = __expf(fminf(-o, 25.f));
    float u2 = u * u;
    return (1.f - u2) / ((1.f + u2) * (1.f + u));
}
__device__ __forceinline__ float geluf(float y) {
    float u = 0.7978845608028654f * fmaf(0.044715f*y, y*y, y);
    float e = __expf(fminf(-2.f*u, 80.f));
    float th = (1.f - e) / (1.f + e);
    return 0.5f*y*(1.f + th);
}

// ---------------- scratch ----------------
__device__ float g_tb[BB*HH];
__device__ float g_wr[HH*NS], g_wi[HH*NS];
__device__ float g_c0r[HH*NS], g_c0i[HH*NS], g_c1r[HH*NS], g_c1i[HH*NS];
__device__ float g_z [BHL];
__device__ float g_yf[BHL];   // fwd scan out; after ticket: gelu(yf + yb + D*z)
__device__ float g_yb[BHL];   // bwd scan out (+ D*z folded)
__device__ int   g_cnt[BB*HH];

// ---------------- zero tickets ----------------
__global__ void k_zero()
{
    g_cnt[blockIdx.x*256 + threadIdx.x] = 0;
}

// ---------------- t @ Wt^T + bt ----------------
__global__ void k_tb(const float* __restrict__ t, const float* __restrict__ Wt,
                     const float* __restrict__ bt)
{
    __shared__ float ts[HH];
    int b = blockIdx.x, h = threadIdx.x;
    ts[h] = t[b*HH + h];
    __syncthreads();
    float acc = bt[h];
    const float* wrow = Wt + (size_t)h*HH;
    #pragma unroll 8
    for (int k = 0; k < HH; k++) acc = fmaf(ts[k], wrow[k], acc);
    g_tb[b*HH + h] = acc;
}

// ---------------- SSM parameter prep ----------------
__global__ void k_ssm(const float* __restrict__ log_dt, const float* __restrict__ logA_real,
                      const float* __restrict__ A_imag, const float* __restrict__ C_re,
                      const float* __restrict__ C_im)
{
    int i = blockIdx.x*blockDim.x + threadIdx.x;
    if (i >= HH*NS) return;
    int h = i / NS;
    float dt = expf(log_dt[h]);
    float Ar = -expf(logA_real[i]);
    float Ai = A_imag[i];
    float dr = dt*Ar, di = dt*Ai;
    float er = expf(dr);
    float wr = er*cosf(di), wi = er*sinf(di);
    g_wr[i] = wr; g_wi[i] = wi;
    float Er = wr - 1.0f, Ei = wi;
    float inv = 1.0f/(Ar*Ar + Ai*Ai);
    float qr = (Er*Ar + Ei*Ai)*inv;
    float qi = (Ei*Ar - Er*Ai)*inv;
    {
        float cr = C_re[i], ci = C_im[i];
        g_c0r[i] = 2.0f*(cr*qr - ci*qi);
        g_c0i[i] = 2.0f*(cr*qi + ci*qr);
    }
    {
        float cr = C_re[HH*NS + i], ci = C_im[HH*NS + i];
        g_c1r[i] = 2.0f*(cr*qr - ci*qi);
        g_c1i[i] = 2.0f*(cr*qi + ci*qr);
    }
}

// ---------------- LayerNorm over H -> z ----------------
__global__ void k_ln(const float* __restrict__ x, const float* __restrict__ ln_g,
                     const float* __restrict__ ln_b)
{
    __shared__ float tbs[HH], gs[HH], bs[HH];
    int b = blockIdx.y;
    int l = blockIdx.x*256 + threadIdx.x;
    tbs[threadIdx.x] = g_tb[b*HH + threadIdx.x];
    gs[threadIdx.x]  = ln_g[threadIdx.x];
    bs[threadIdx.x]  = ln_b[threadIdx.x];
    __syncthreads();
    const float* xb = x + (size_t)b*HH*LL + l;
    float s = 0.f, ss = 0.f;
    #pragma unroll 8
    for (int h = 0; h < HH; h++) {
        float v = xb[(size_t)h*LL] + tbs[h];
        s += v; ss = fmaf(v, v, ss);
    }
    float mu  = s * (1.0f/HH);
    float var = ss*(1.0f/HH) - mu*mu;
    float rstd = rsqrtf(var + 1e-5f);
    float* zb = g_z + (size_t)b*HH*LL + l;
    #pragma unroll 8
    for (int h = 0; h < HH; h++) {
        float v = xb[(size_t)h*LL] + tbs[h];
        zb[(size_t)h*LL] = (v - mu)*rstd*gs[h] + bs[h];
    }
}

// ---------------- scan (R4 structure) + fused gelu ticket ----------------
#define SCAN_WPB 4
__global__ __launch_bounds__(32*SCAN_WPB) void k_scan(const float* __restrict__ Dv)
{
    __shared__ __align__(16) float pbuf[SCAN_WPB][32*33];
    __shared__ __align__(16) u64   zbuf[SCAN_WPB][32];
    int wid  = threadIdx.x >> 5;
    int lane = threadIdx.x & 31;
    int gw   = blockIdx.x*SCAN_WPB + wid;   // 0 .. 2*B*H-1
    int bh   = gw >> 1;
    int dir  = gw & 1;
    int h    = bh & (HH-1);
    int ci   = h*NS + lane;
    float* pw = pbuf[wid];
    u64*   zw = zbuf[wid];

    u64 wr2  = pk2(g_wr[ci],  g_wr[ci+32]);
    u64 wi2  = pk2(g_wi[ci],  g_wi[ci+32]);
    u64 wi2n = pk2(-g_wi[ci], -g_wi[ci+32]);
    u64 cr2, ci2n;
    if (dir == 0) { cr2 = pk2(g_c0r[ci], g_c0r[ci+32]); ci2n = pk2(-g_c0i[ci], -g_c0i[ci+32]); }
    else          { cr2 = pk2(g_c1r[ci], g_c1r[ci+32]); ci2n = pk2(-g_c1i[ci], -g_c1i[ci+32]); }

    const float* zp = g_z + (size_t)bh*LL;
    float* yp = (dir == 0 ? g_yf : g_yb) + (size_t)bh*LL;

    u64 sr = 0ULL, si = 0ULL;

    if (dir == 0) {
        for (int t = 0; t < LL/32; t++) {
            int l0 = t*32;
            float zv = zp[l0 + lane];
            zw[lane] = pk2(zv, zv);
            __syncwarp();
            #pragma unroll
            for (int j = 0; j < 32; j++) {
                u64 z2  = zw[j];
                u64 nsr = fma2(wr2, sr, fma2(wi2n, si, z2));
                si = fma2(wr2, si, mul2(wi2, sr));
                sr = nsr;
                u64 p2 = fma2(cr2, sr, mul2(ci2n, si));
                float pa, pb; up2(p2, pa, pb);
                pw[j*33 + lane] = pa + pb;
            }
            __syncwarp();
            float acc = 0.f;
            #pragma unroll
            for (int k = 0; k < 32; k++) acc += pw[lane*33 + k];
            yp[l0 + lane] = acc;
            __syncwarp();
        }
    } else {
        float d = Dv[h];
        for (int t = 0; t < LL/32; t++) {
            int l0 = LL - 32*(t+1);
            float zv = zp[l0 + lane];
            zw[lane] = pk2(zv, zv);
            __syncwarp();
            #pragma unroll
            for (int j = 31; j >= 0; j--) {
                // emit contribution from state BEFORE absorbing z[l0+j]
                u64 p2 = fma2(cr2, sr, mul2(ci2n, si));
                float pa, pb; up2(p2, pa, pb);
                pw[j*33 + lane] = pa + pb;
                u64 z2  = zw[j];
                u64 nsr = fma2(wr2, sr, fma2(wi2n, si, z2));
                si = fma2(wr2, si, mul2(wi2, sr));
                sr = nsr;
            }
            __syncwarp();
            float acc = 0.f;
            #pragma unroll
            for (int k = 0; k < 32; k++) acc += pw[lane*33 + k];
            yp[l0 + lane] = fmaf(d, zv, acc);   // fold D*z into bwd output
            __syncwarp();
        }
    }

    // ---- ticket: second finisher for this (b,h) row applies gelu(yf+yb) -> g_yf ----
    __threadfence();
    int old = 0;
    if (lane == 0) old = atomicAdd(&g_cnt[bh], 1);
    old = __shfl_sync(0xffffffffu, old, 0);
    if (old == 1) {
        __threadfence();
        const float4* fa = (const float4*)(g_yf + (size_t)bh*LL);
        const float4* fb = (const float4*)(g_yb + (size_t)bh*LL);
        float4*       fo = (float4*)      (g_yf + (size_t)bh*LL);
        #pragma unroll
        for (int i = lane; i < LL/4; i += 32) {
            float4 a = fa[i], b = fb[i];
            float4 o;
            o.x = geluf(a.x + b.x);
            o.y = geluf(a.y + b.y);
            o.z = geluf(a.z + b.z);
            o.w = geluf(a.w + b.w);
            fo[i] = o;
        }
    }
}

// ---------------- stage1: 128x64 tile ----------------
__global__ __launch_bounds__(256) void k_stage1(const float* __restrict__ Wout, const float* __restrict__ bout,
                         const float* __restrict__ x, const float* __restrict__ feat,
                         const float* __restrict__ Wf, const float* __restrict__ bf)
{
    __shared__ __align__(16) float Ws[16][130];
    __shared__ __align__(16) float Bs[16][65];
    const int b  = blockIdx.z;
    const int g0 = blockIdx.y * 128;
    const int l0 = blockIdx.x * 64;
    const int tid = threadIdx.x;
    const int tx = tid & 15, ty = tid >> 4;
    const int arow = tid >> 1, akg = (tid & 1) * 8;
    const int brow = tid >> 4, bc0 = tid & 15;

    u64 acc[4][4];
    #pragma unroll
    for (int r = 0; r < 4; r++)
        #pragma unroll
        for (int j = 0; j < 4; j++) acc[r][j] = 0ULL;

    const float* act = g_yf + (size_t)b*HH*LL;
    for (int k0 = 0; k0 < HH; k0 += 16) {
        float4 w0 = *(const float4*)(Wout + (size_t)(g0+arow)*HH + k0 + akg);
        float4 w1 = *(const float4*)(Wout + (size_t)(g0+arow)*HH + k0 + akg + 4);
        Ws[akg+0][arow]=w0.x; Ws[akg+1][arow]=w0.y; Ws[akg+2][arow]=w0.z; Ws[akg+3][arow]=w0.w;
        Ws[akg+4][arow]=w1.x; Ws[akg+5][arow]=w1.y; Ws[akg+6][arow]=w1.z; Ws[akg+7][arow]=w1.w;
        #pragma unroll
        for (int c = 0; c < 4; c++)
            Bs[brow][bc0 + 16*c] = act[(size_t)(k0+brow)*LL + l0 + bc0 + 16*c];
        __syncthreads();
        #pragma unroll
        for (int k = 0; k < 16; k++) {
            u64 ap[4], bp[4];
            #pragma unroll
            for (int r = 0; r < 4; r++) ap[r] = *(const u64*)&Ws[k][ty*8 + 2*r];
            #pragma unroll
            for (int j = 0; j < 4; j++) { float v = Bs[k][16*j + tx]; bp[j] = pk2(v, v); }
            #pragma unroll
            for (int r = 0; r < 4; r++)
                #pragma unroll
                for (int j = 0; j < 4; j++)
                    acc[r][j] = fma2(ap[r], bp[j], acc[r][j]);
        }
        __syncthreads();
    }
    const float* fb = feat + (size_t)b*FF*LL;
    for (int k0 = 0; k0 < FF; k0 += 16) {
        float4 w0 = *(const float4*)(Wf + (size_t)(g0+arow)*FF + k0 + akg);
        float4 w1 = *(const float4*)(Wf + (size_t)(g0+arow)*FF + k0 + akg + 4);
        Ws[akg+0][arow]=w0.x; Ws[akg+1][arow]=w0.y; Ws[akg+2][arow]=w0.z; Ws[akg+3][arow]=w0.w;
        Ws[akg+4][arow]=w1.x; Ws[akg+5][arow]=w1.y; Ws[akg+6][arow]=w1.z; Ws[akg+7][arow]=w1.w;
        #pragma unroll
        for (int c = 0; c < 4; c++)
            Bs[brow][bc0 + 16*c] = fb[(size_t)(k0+brow)*LL + l0 + bc0 + 16*c];
        __syncthreads();
        #pragma unroll
        for (int k = 0; k < 16; k++) {
            u64 ap[4], bp[4];
            #pragma unroll
            for (int r = 0; r < 4; r++) ap[r] = *(const u64*)&Ws[k][ty*8 + 2*r];
            #pragma unroll
            for (int j = 0; j < 4; j++) { float v = Bs[k][16*j + tx]; bp[j] = pk2(v, v); }
            #pragma unroll
            for (int r = 0; r < 4; r++)
                #pragma unroll
                for (int j = 0; j < 4; j++)
                    acc[r][j] = fma2(ap[r], bp[j], acc[r][j]);
        }
        __syncthreads();
    }
    float base[8];
    #pragma unroll
    for (int i = 0; i < 8; i++) {
        int g = g0 + ty*8 + i;
        base[i] = bout[g] + bf[g] + g_tb[b*HH + g];
    }
    #pragma unroll
    for (int r = 0; r < 4; r++) {
        int g = g0 + ty*8 + 2*r;
        #pragma unroll
        for (int j = 0; j < 4; j++) {
            float v0, v1; up2(acc[r][j], v0, v1);
            int col = l0 + 16*j + tx;
            size_t off0 = ((size_t)b*HH + g)*LL + col;
            size_t off1 = off0 + LL;
            float o0 = v0 + base[2*r]   + x[off0];
            float o1 = v1 + base[2*r+1] + x[off1];
            g_z[off0] = gatef(o0);
            g_z[off1] = gatef(o1);
        }
    }
}

// ---------------- stage2: o1 = W1@g + b1 + x ; o2 = W2@g + b2 ----------------
__global__ __launch_bounds__(256) void k_stage2(const float* __restrict__ W1, const float* __restrict__ b1,
                         const float* __restrict__ W2, const float* __restrict__ b2,
                         const float* __restrict__ x, float* __restrict__ o1,
                         float* __restrict__ o2)
{
    __shared__ __align__(16) float W1s[16][130];
    __shared__ __align__(16) float W2s[16][130];
    __shared__ __align__(16) float Bs[16][65];
    const int b  = blockIdx.z;
    const int g0 = blockIdx.y * 128;
    const int l0 = blockIdx.x * 64;
    const int tid = threadIdx.x;
    const int tx = tid & 15, ty = tid >> 4;
    const int arow = tid >> 1, akg = (tid & 1) * 8;
    const int brow = tid >> 4, bc0 = tid & 15;

    u64 acc1[4][4], acc2[4][4];
    #pragma unroll
    for (int r = 0; r < 4; r++)
        #pragma unroll
        for (int j = 0; j < 4; j++) { acc1[r][j] = 0ULL; acc2[r][j] = 0ULL; }

    const float* gb = g_z + (size_t)b*HH*LL;
    for (int k0 = 0; k0 < HH; k0 += 16) {
        float4 w0 = *(const float4*)(W1 + (size_t)(g0+arow)*HH + k0 + akg);
        float4 w1 = *(const float4*)(W1 + (size_t)(g0+arow)*HH + k0 + akg + 4);
        W1s[akg+0][arow]=w0.x; W1s[akg+1][arow]=w0.y; W1s[akg+2][arow]=w0.z; W1s[akg+3][arow]=w0.w;
        W1s[akg+4][arow]=w1.x; W1s[akg+5][arow]=w1.y; W1s[akg+6][arow]=w1.z; W1s[akg+7][arow]=w1.w;
        float4 v0 = *(const float4*)(W2 + (size_t)(g0+arow)*HH + k0 + akg);
        float4 v1 = *(const float4*)(W2 + (size_t)(g0+arow)*HH + k0 + akg + 4);
        W2s[akg+0][arow]=v0.x; W2s[akg+1][arow]=v0.y; W2s[akg+2][arow]=v0.z; W2s[akg+3][arow]=v0.w;
        W2s[akg+4][arow]=v1.x; W2s[akg+5][arow]=v1.y; W2s[akg+6][arow]=v1.z; W2s[akg+7][arow]=v1.w;
        #pragma unroll
        for (int c = 0; c < 4; c++)
            Bs[brow][bc0 + 16*c] = gb[(size_t)(k0+brow)*LL + l0 + bc0 + 16*c];
        __syncthreads();
        #pragma unroll
        for (int k = 0; k < 16; k++) {
            u64 a1[4], a2[4], bp[4];
            #pragma unroll
            for (int r = 0; r < 4; r++) a1[r] = *(const u64*)&W1s[k][ty*8 + 2*r];
            #pragma unroll
            for (int r = 0; r < 4; r++) a2[r] = *(const u64*)&W2s[k][ty*8 + 2*r];
            #pragma unroll
            for (int j = 0; j < 4; j++) { float v = Bs[k][16*j + tx]; bp[j] = pk2(v, v); }
            #pragma unroll
            for (int r = 0; r < 4; r++)
                #pragma unroll
                for (int j = 0; j < 4; j++) {
                    acc1[r][j] = fma2(a1[r], bp[j], acc1[r][j]);
                    acc2[r][j] = fma2(a2[r], bp[j], acc2[r][j]);
                }
        }
        __syncthreads();
    }
    #pragma unroll
    for (int r = 0; r < 4; r++) {
        int g = g0 + ty*8 + 2*r;
        float bb1a = b1[g], bb1b = b1[g+1];
        float bb2a = b2[g], bb2b = b2[g+1];
        #pragma unroll
        for (int j = 0; j < 4; j++) {
            int col = l0 + 16*j + tx;
            size_t off0 = ((size_t)b*HH + g)*LL + col;
            size_t off1 = off0 + LL;
            float p0, p1, q0, q1;
            up2(acc1[r][j], p0, p1);
            up2(acc2[r][j], q0, q1);
            o1[off0] = p0 + bb1a + x[off0];
            o1[off1] = p1 + bb1b + x[off1];
            o2[off0] = q0 + bb2a;
            o2[off1] = q1 + bb2b;
        }
    }
}

// ---------------- launch ----------------
extern "C" void kernel_launch(void* const* d_in, const int* in_sizes, int n_in,
                              void* d_out, int out_size)
{
    const float* x        = (const float*)d_in[0];
    const float* t        = (const float*)d_in[1];
    const float* feat     = (const float*)d_in[2];
    const float* Wt       = (const float*)d_in[3];
    const float* bt       = (const float*)d_in[4];
    const float* ln_g     = (const float*)d_in[5];
    const float* ln_b     = (const float*)d_in[6];
    const float* log_dt   = (const float*)d_in[7];
    const float* logA_real= (const float*)d_in[8];
    const float* A_imag   = (const float*)d_in[9];
    const float* C_re     = (const float*)d_in[10];
    const float* C_im     = (const float*)d_in[11];
    const float* Dv       = (const float*)d_in[12];
    const float* Wout     = (const float*)d_in[13];
    const float* bout     = (const float*)d_in[14];
    const float* W1       = (const float*)d_in[15];
    const float* b1       = (const float*)d_in[16];
    const float* W2       = (const float*)d_in[17];
    const float* b2       = (const float*)d_in[18];
    const float* Wf       = (const float*)d_in[19];
    const float* bf       = (const float*)d_in[20];

    float* o1 = (float*)d_out;
    float* o2 = (float*)d_out + (size_t)BHL;

    k_zero<<<(BB*HH)/256, 256>>>();
    k_tb<<<BB, 256>>>(t, Wt, bt);
    k_ssm<<<(HH*NS+255)/256, 256>>>(log_dt, logA_real, A_imag, C_re, C_im);
    k_ln<<<dim3(LL/256, BB), 256>>>(x, ln_g, ln_b);
    k_scan<<<(2*BB*HH)/SCAN_WPB, 32*SCAN_WPB>>>(Dv);
    k_stage1<<<dim3(LL/64, HH/128, BB), 256>>>(Wout, bout, x, feat, Wf, bf);
    k_stage2<<<dim3(LL/64, HH/128, BB), 256>>>(W1, b1, W2, b2, x, o1, o2);
}